// round 1
// baseline (speedup 1.0000x reference)
#include <cuda_runtime.h>
#include <math.h>

#define TSEQ 2048
#define DMODEL 4096
#define NQ 32
#define NKV 8
#define HD 128

// Scratch (static device globals; no runtime allocation)
__device__ float g_q[TSEQ * NQ * HD];    // [t][n][h]
__device__ float g_k[TSEQ * NKV * HD];   // [t][kh][h]
__device__ float g_v[TSEQ * NKV * HD];   // [t][kh][h]
__device__ float g_o[TSEQ * NQ * HD];    // attention output [t][n][h]

// ---------------------------------------------------------------------------
// 128x128 tile SGEMM (BK=16), 256 threads, 8x8 register micro-tiles.
// A: row-major [.. x K] starting at the row block, stride lda
// B: row-major [K x ..] starting at the col block, stride ldb
// C: row-major output starting at (rowblock, colblock), stride ldc
// Requires K % 16 == 0, full tiles, 16B-aligned pointers.
// ---------------------------------------------------------------------------
__device__ __forceinline__ void sgemm_128x128(
    const float* __restrict__ A, const float* __restrict__ B,
    float* __restrict__ C, int K, int lda, int ldb, int ldc)
{
    __shared__ float As[16][132];  // [k][m], padded for conflict-free access
    __shared__ float Bs[16][128];  // [k][n]

    const int tid = threadIdx.x;       // 0..255
    const int tx = tid & 15;
    const int ty = tid >> 4;

    float acc[8][8];
#pragma unroll
    for (int i = 0; i < 8; i++)
#pragma unroll
        for (int j = 0; j < 8; j++) acc[i][j] = 0.f;

    for (int kb = 0; kb < K; kb += 16) {
        // Load A tile: 128 rows x 16 k (512 float4), transpose into As[k][m]
#pragma unroll
        for (int i = 0; i < 2; i++) {
            int idx = tid + i * 256;          // 0..511
            int row = idx >> 2;               // 0..127
            int kq  = (idx & 3) * 4;          // 0,4,8,12
            float4 v = *(const float4*)(A + (size_t)row * lda + kb + kq);
            As[kq + 0][row] = v.x;
            As[kq + 1][row] = v.y;
            As[kq + 2][row] = v.z;
            As[kq + 3][row] = v.w;
        }
        // Load B tile: 16 rows x 128 cols (512 float4), direct
#pragma unroll
        for (int i = 0; i < 2; i++) {
            int idx = tid + i * 256;
            int kk = idx >> 5;                // 0..15
            int n4 = (idx & 31) * 4;          // 0..124
            *(float4*)&Bs[kk][n4] = *(const float4*)(B + (size_t)(kb + kk) * ldb + n4);
        }
        __syncthreads();

#pragma unroll
        for (int k = 0; k < 16; k++) {
            float a[8], b[8];
            *(float4*)&a[0] = *(const float4*)&As[k][ty * 8];
            *(float4*)&a[4] = *(const float4*)&As[k][ty * 8 + 4];
            *(float4*)&b[0] = *(const float4*)&Bs[k][tx * 8];
            *(float4*)&b[4] = *(const float4*)&Bs[k][tx * 8 + 4];
#pragma unroll
            for (int i = 0; i < 8; i++)
#pragma unroll
                for (int j = 0; j < 8; j++)
                    acc[i][j] = fmaf(a[i], b[j], acc[i][j]);
        }
        __syncthreads();
    }

#pragma unroll
    for (int i = 0; i < 8; i++) {
        float* cr = C + (size_t)(ty * 8 + i) * ldc + tx * 8;
        *(float4*)cr       = make_float4(acc[i][0], acc[i][1], acc[i][2], acc[i][3]);
        *(float4*)(cr + 4) = make_float4(acc[i][4], acc[i][5], acc[i][6], acc[i][7]);
    }
}

// ---------------------------------------------------------------------------
// QKV projection: grid (16 row tiles, 48 heads). Heads 0..31 Q, 32..39 K, 40..47 V.
// ---------------------------------------------------------------------------
__global__ __launch_bounds__(256) void qkv_gemm_kernel(
    const float* __restrict__ x, const float* __restrict__ q_w,
    const float* __restrict__ kv_w)
{
    const int rowBlk = blockIdx.x;   // 0..15
    const int h = blockIdx.y;        // 0..47
    const float* A = x + (size_t)rowBlk * 128 * DMODEL;
    const float* B;
    float* C;
    int ldc;
    if (h < NQ) {
        B = q_w + (size_t)h * DMODEL * HD;
        C = g_q + (size_t)rowBlk * 128 * (NQ * HD) + h * HD;
        ldc = NQ * HD;
    } else if (h < NQ + NKV) {
        int kh = h - NQ;
        B = kv_w + (size_t)kh * DMODEL * HD;                 // kv_w[0][kh]
        C = g_k + (size_t)rowBlk * 128 * (NKV * HD) + kh * HD;
        ldc = NKV * HD;
    } else {
        int vh = h - NQ - NKV;
        B = kv_w + (size_t)(NKV + vh) * DMODEL * HD;         // kv_w[1][vh]
        C = g_v + (size_t)rowBlk * 128 * (NKV * HD) + vh * HD;
        ldc = NKV * HD;
    }
    sgemm_128x128(A, B, C, DMODEL, DMODEL, HD, ldc);
}

// ---------------------------------------------------------------------------
// RMSNorm (+ (1+scale) for q/k, plain for v) + RoPE (q/k only), in place.
// grid (48 heads, 2048 t), 128 threads.
// ---------------------------------------------------------------------------
__global__ __launch_bounds__(128) void normrope_kernel(
    const int* __restrict__ seg_pos, const float* __restrict__ q_scale,
    const float* __restrict__ k_scale)
{
    const int h = blockIdx.x;   // 0..47
    const int t = blockIdx.y;
    const int d = threadIdx.x;  // 0..127

    float* row;
    const float* sc;
    bool dorope;
    if (h < NQ)            { row = g_q + ((size_t)t * NQ + h) * HD;         sc = q_scale; dorope = true; }
    else if (h < NQ + NKV) { row = g_k + ((size_t)t * NKV + (h - NQ)) * HD; sc = k_scale; dorope = true; }
    else                   { row = g_v + ((size_t)t * NKV + (h - NQ - NKV)) * HD; sc = nullptr; dorope = false; }

    float v = row[d];
    float ss = v * v;
#pragma unroll
    for (int m = 16; m >= 1; m >>= 1) ss += __shfl_xor_sync(0xffffffffu, ss, m);
    __shared__ float red[4];
    if ((d & 31) == 0) red[d >> 5] = ss;
    __syncthreads();
    ss = red[0] + red[1] + red[2] + red[3];

    float rms = rsqrtf(ss * (1.0f / 128.0f) + 1e-6f);
    float scale = sc ? (1.0f + sc[d]) : 1.0f;
    float nv = v * rms * scale;

    if (!dorope) { row[d] = nv; return; }

    __shared__ float sh[128];
    sh[d] = nv;
    __syncthreads();
    if (d < 64) {
        float x1 = sh[d];
        float x2 = sh[d + 64];
        float pos = (float)seg_pos[t];
        float fraction = (2.0f * (float)d) * (1.0f / 128.0f);
        float timescale = powf(10000.0f, fraction);
        float ang = pos / timescale;
        float s, c;
        __sincosf(ang, &s, &c);   // fast path; refine if precision is marginal
        // use accurate versions to stay well under 1e-3:
        s = sinf(ang); c = cosf(ang);
        row[d]      = x1 * c - x2 * s;
        row[d + 64] = x2 * c + x1 * s;
    }
}

// ---------------------------------------------------------------------------
// Flash attention, 64 q-rows x 64 keys tiles, online softmax, causal.
// grid (32 q-tiles, 32 heads), 256 threads, dynamic smem ~113KB.
// Thread map: tx=tid&15, ty=tid>>4. S-phase: 4x4 micro-tile. AV: rows x 8 h-cols.
// ---------------------------------------------------------------------------
#define FLASH_SMEM_FLOATS (8192 + 8192 + 8192 + 64 * 68)
#define FLASH_SMEM_BYTES  (FLASH_SMEM_FLOATS * 4)

__global__ __launch_bounds__(256) void flash_kernel()
{
    extern __shared__ float smem[];
    float* Qs = smem;             // [d][m]  128*64
    float* Ks = smem + 8192;      // [d][s]  128*64
    float* Vs = smem + 16384;     // [s][h]  64*128
    float* Ps = smem + 24576;     // [m][s]  64*68 (pad keeps 16B alignment)

    const int qt   = blockIdx.x;      // 0..31
    const int head = blockIdx.y;      // 0..31
    const int kvh  = head >> 2;       // GQA group of 4
    const int tid  = threadIdx.x;
    const int tx = tid & 15;
    const int ty = tid >> 4;
    const int t0 = qt * 64;

    // Load Q tile transposed: Qs[d][m]
#pragma unroll
    for (int i = 0; i < 8; i++) {
        int idx = tid + i * 256;              // 0..2047 float4s
        int m  = idx >> 5;                    // 0..63
        int d4 = (idx & 31) * 4;              // 0..124
        float4 v = *(const float4*)(g_q + ((size_t)(t0 + m) * NQ + head) * HD + d4);
        Qs[(d4 + 0) * 64 + m] = v.x;
        Qs[(d4 + 1) * 64 + m] = v.y;
        Qs[(d4 + 2) * 64 + m] = v.z;
        Qs[(d4 + 3) * 64 + m] = v.w;
    }

    float acc[4][8];
    float mrow[4], lrow[4];
#pragma unroll
    for (int i = 0; i < 4; i++) {
        mrow[i] = -INFINITY;
        lrow[i] = 0.f;
#pragma unroll
        for (int hh = 0; hh < 8; hh++) acc[i][hh] = 0.f;
    }

    const int ntiles = qt + 1;
    for (int j = 0; j < ntiles; j++) {
        const int s0 = j * 64;
        __syncthreads();  // previous AV done before overwriting K/V/P

        // Load K tile transposed + V tile direct
#pragma unroll
        for (int i = 0; i < 8; i++) {
            int idx = tid + i * 256;
            int s  = idx >> 5;
            int d4 = (idx & 31) * 4;
            size_t base = ((size_t)(s0 + s) * NKV + kvh) * HD + d4;
            float4 kv = *(const float4*)(g_k + base);
            Ks[(d4 + 0) * 64 + s] = kv.x;
            Ks[(d4 + 1) * 64 + s] = kv.y;
            Ks[(d4 + 2) * 64 + s] = kv.z;
            Ks[(d4 + 3) * 64 + s] = kv.w;
            *(float4*)&Vs[s * 128 + d4] = *(const float4*)(g_v + base);
        }
        __syncthreads();

        // S = Q K^T (4x4 per thread)
        float sacc[4][4];
#pragma unroll
        for (int i = 0; i < 4; i++)
#pragma unroll
            for (int jj = 0; jj < 4; jj++) sacc[i][jj] = 0.f;

#pragma unroll 8
        for (int d = 0; d < 128; d++) {
            float4 qv = *(const float4*)(Qs + d * 64 + ty * 4);
            float4 kv = *(const float4*)(Ks + d * 64 + tx * 4);
            float qa[4] = {qv.x, qv.y, qv.z, qv.w};
            float kb[4] = {kv.x, kv.y, kv.z, kv.w};
#pragma unroll
            for (int i = 0; i < 4; i++)
#pragma unroll
                for (int jj = 0; jj < 4; jj++)
                    sacc[i][jj] = fmaf(qa[i], kb[jj], sacc[i][jj]);
        }

        const bool diag = (j == qt);
#pragma unroll
        for (int i = 0; i < 4; i++) {
            const int tg = t0 + ty * 4 + i;
            if (diag) {
#pragma unroll
                for (int jj = 0; jj < 4; jj++)
                    if (s0 + tx * 4 + jj > tg) sacc[i][jj] = -INFINITY;
            }
            float mt = fmaxf(fmaxf(sacc[i][0], sacc[i][1]), fmaxf(sacc[i][2], sacc[i][3]));
#pragma unroll
            for (int mm = 8; mm >= 1; mm >>= 1)
                mt = fmaxf(mt, __shfl_xor_sync(0xffffffffu, mt, mm));
            float mnew = fmaxf(mrow[i], mt);
            float alpha = expf(mrow[i] - mnew);
            float pv[4];
            float ps = 0.f;
#pragma unroll
            for (int jj = 0; jj < 4; jj++) {
                float p = expf(sacc[i][jj] - mnew);
                pv[jj] = p;
                ps += p;
            }
#pragma unroll
            for (int mm = 8; mm >= 1; mm >>= 1)
                ps += __shfl_xor_sync(0xffffffffu, ps, mm);
            lrow[i] = lrow[i] * alpha + ps;
            mrow[i] = mnew;
#pragma unroll
            for (int hh = 0; hh < 8; hh++) acc[i][hh] *= alpha;
            *(float4*)(Ps + (ty * 4 + i) * 68 + tx * 4) =
                make_float4(pv[0], pv[1], pv[2], pv[3]);
        }
        __syncthreads();

        // AV accumulate: acc[i][0..7] over 64 keys
#pragma unroll 4
        for (int s = 0; s < 64; s++) {
            float4 v0 = *(const float4*)&Vs[s * 128 + tx * 8];
            float4 v1 = *(const float4*)&Vs[s * 128 + tx * 8 + 4];
#pragma unroll
            for (int i = 0; i < 4; i++) {
                float p = Ps[(ty * 4 + i) * 68 + s];
                acc[i][0] = fmaf(p, v0.x, acc[i][0]);
                acc[i][1] = fmaf(p, v0.y, acc[i][1]);
                acc[i][2] = fmaf(p, v0.z, acc[i][2]);
                acc[i][3] = fmaf(p, v0.w, acc[i][3]);
                acc[i][4] = fmaf(p, v1.x, acc[i][4]);
                acc[i][5] = fmaf(p, v1.y, acc[i][5]);
                acc[i][6] = fmaf(p, v1.z, acc[i][6]);
                acc[i][7] = fmaf(p, v1.w, acc[i][7]);
            }
        }
    }

    // Normalize and write out
#pragma unroll
    for (int i = 0; i < 4; i++) {
        float inv = 1.0f / lrow[i];
        float* op = g_o + ((size_t)(t0 + ty * 4 + i) * NQ + head) * HD + tx * 8;
        *(float4*)op =
            make_float4(acc[i][0] * inv, acc[i][1] * inv, acc[i][2] * inv, acc[i][3] * inv);
        *(float4*)(op + 4) =
            make_float4(acc[i][4] * inv, acc[i][5] * inv, acc[i][6] * inv, acc[i][7] * inv);
    }
}

// ---------------------------------------------------------------------------
// O projection: out[T,D] = g_o[T, N*H] @ o_w[N*H, D]
// grid (32 col tiles, 16 row tiles)
// ---------------------------------------------------------------------------
__global__ __launch_bounds__(256) void oproj_kernel(
    const float* __restrict__ o_w, float* __restrict__ out)
{
    const int colBlk = blockIdx.x;  // 0..31
    const int rowBlk = blockIdx.y;  // 0..15
    sgemm_128x128(g_o + (size_t)rowBlk * 128 * (NQ * HD),
                  o_w + (size_t)colBlk * 128,
                  out + (size_t)rowBlk * 128 * DMODEL + colBlk * 128,
                  NQ * HD, NQ * HD, DMODEL, DMODEL);
}

// ---------------------------------------------------------------------------
extern "C" void kernel_launch(void* const* d_in, const int* in_sizes, int n_in,
                              void* d_out, int out_size)
{
    const float* x       = (const float*)d_in[0];
    const int*   seg     = (const int*)d_in[1];
    // d_in[2] = attn_mask (exactly causal by construction; applied analytically)
    const float* q_w     = (const float*)d_in[3];
    const float* kv_w    = (const float*)d_in[4];
    const float* o_w     = (const float*)d_in[5];
    const float* q_scale = (const float*)d_in[6];
    const float* k_scale = (const float*)d_in[7];
    float* out = (float*)d_out;

    cudaFuncSetAttribute(flash_kernel, cudaFuncAttributeMaxDynamicSharedMemorySize,
                         FLASH_SMEM_BYTES);

    qkv_gemm_kernel<<<dim3(16, 48), 256>>>(x, q_w, kv_w);
    normrope_kernel<<<dim3(48, TSEQ), 128>>>(seg, q_scale, k_scale);
    flash_kernel<<<dim3(32, 32), 256, FLASH_SMEM_BYTES>>>();
    oproj_kernel<<<dim3(32, 16), 256>>>(o_w, out);
}

// round 3
// speedup vs baseline: 2.8290x; 2.8290x over previous
#include <cuda_runtime.h>
#include <cuda_bf16.h>
#include <math.h>
#include <stdint.h>

#define TSEQ 2048
#define DMODEL 4096
#define NQ 32
#define NKV 8
#define HD 128

// Scratch (static device globals; no runtime allocation)
__device__ float g_q[TSEQ * NQ * HD];    // [t][n][h]
__device__ float g_k[TSEQ * NKV * HD];   // [t][kh][h]
__device__ float g_v[TSEQ * NKV * HD];   // [t][kh][h]
__device__ float g_o[TSEQ * NQ * HD];    // attention output [t][n][h]

// ===========================================================================
// mma.sync helpers (sm_80+ portable; no arch-specific features)
// ===========================================================================
__device__ __forceinline__ uint32_t smem_u32(const void* p) {
    uint32_t a;
    asm("{ .reg .u64 t; cvta.to.shared.u64 t, %1; cvt.u32.u64 %0, t; }"
        : "=r"(a) : "l"(p));
    return a;
}

__device__ __forceinline__ void ldsm_x4(uint32_t& r0, uint32_t& r1,
                                        uint32_t& r2, uint32_t& r3, uint32_t a) {
    asm volatile("ldmatrix.sync.aligned.m8n8.x4.shared.b16 {%0,%1,%2,%3}, [%4];"
                 : "=r"(r0), "=r"(r1), "=r"(r2), "=r"(r3) : "r"(a));
}
__device__ __forceinline__ void ldsm_x4t(uint32_t& r0, uint32_t& r1,
                                         uint32_t& r2, uint32_t& r3, uint32_t a) {
    asm volatile("ldmatrix.sync.aligned.m8n8.x4.trans.shared.b16 {%0,%1,%2,%3}, [%4];"
                 : "=r"(r0), "=r"(r1), "=r"(r2), "=r"(r3) : "r"(a));
}

__device__ __forceinline__ void mma16816(float* d, const uint32_t* a, const uint32_t* b) {
    asm volatile(
        "mma.sync.aligned.m16n8k16.row.col.f32.bf16.bf16.f32 "
        "{%0,%1,%2,%3}, {%4,%5,%6,%7}, {%8,%9}, {%0,%1,%2,%3};"
        : "+f"(d[0]), "+f"(d[1]), "+f"(d[2]), "+f"(d[3])
        : "r"(a[0]), "r"(a[1]), "r"(a[2]), "r"(a[3]), "r"(b[0]), "r"(b[1]));
}

// ===========================================================================
// bf16-split GEMM via mma.sync: C[128x128] = A[128xK] * B[Kx128]  (fp32 in/out)
//   A row-major (lda), B row-major (ldb), C row-major (ldc). K % 32 == 0.
//   Split each fp32 into bf16 hi+lo; 3 passes: AhBh + AlBh + AhBl.
// ===========================================================================
#define BM 128
#define BN 128
#define BK 32
#define APITCH 40    // bf16 elements per A smem row (80 B)
#define BPITCH 136   // bf16 elements per B smem row (272 B)

__device__ __forceinline__ void cvt_hilo(float a, float b,
                                         __nv_bfloat162& h, __nv_bfloat162& l) {
    h = __floats2bfloat162_rn(a, b);
    l = __floats2bfloat162_rn(a - __bfloat162float(h.x), b - __bfloat162float(h.y));
}

__device__ void gemm_mma(const float* __restrict__ A, int lda,
                         const float* __restrict__ B, int ldb,
                         float* __restrict__ C, int ldc, int K)
{
    __shared__ __align__(16) __nv_bfloat16 Ah[BM * APITCH];
    __shared__ __align__(16) __nv_bfloat16 Al[BM * APITCH];
    __shared__ __align__(16) __nv_bfloat16 Bh[BK * BPITCH];
    __shared__ __align__(16) __nv_bfloat16 Bl[BK * BPITCH];

    const int tid  = threadIdx.x;
    const int lane = tid & 31;
    const int wid  = tid >> 5;
    const int wm = (wid & 3) * 32;   // warp row base within tile
    const int wn = (wid >> 2) * 64;  // warp col base within tile
    const int g = lane >> 3;         // ldmatrix group 0..3
    const int r = lane & 7;

    const uint32_t ah_base = smem_u32(Ah);
    const uint32_t al_base = smem_u32(Al);
    const uint32_t bh_base = smem_u32(Bh);
    const uint32_t bl_base = smem_u32(Bl);

    float acc[2][8][4];
#pragma unroll
    for (int i = 0; i < 2; i++)
#pragma unroll
        for (int j = 0; j < 8; j++)
#pragma unroll
            for (int q = 0; q < 4; q++) acc[i][j][q] = 0.f;

    const int nch = K / BK;
    for (int c = 0; c < nch; c++) {
        __syncthreads();   // previous compute done before smem overwrite

        // --- A: 128 rows x 32 k fp32 -> bf16 hi/lo ---
        const float* Ab = A + c * BK;
#pragma unroll
        for (int i = 0; i < 4; i++) {
            int idx = tid + i * 256;        // 0..1023
            int row = idx >> 3;             // 0..127
            int k4  = (idx & 7) * 4;        // 0..28
            float4 v = *(const float4*)(Ab + (size_t)row * lda + k4);
            __nv_bfloat162 h0, l0, h1, l1;
            cvt_hilo(v.x, v.y, h0, l0);
            cvt_hilo(v.z, v.w, h1, l1);
            *(__nv_bfloat162*)(Ah + row * APITCH + k4)     = h0;
            *(__nv_bfloat162*)(Ah + row * APITCH + k4 + 2) = h1;
            *(__nv_bfloat162*)(Al + row * APITCH + k4)     = l0;
            *(__nv_bfloat162*)(Al + row * APITCH + k4 + 2) = l1;
        }

        // --- B: 32 k-rows x 128 n fp32 -> bf16 hi/lo ([k][n] layout) ---
        const float* Bb = B + (size_t)c * BK * ldb;
#pragma unroll
        for (int i = 0; i < 4; i++) {
            int idx = tid + i * 256;
            int kk = idx >> 5;              // 0..31
            int n4 = (idx & 31) * 4;        // 0..124
            float4 v = *(const float4*)(Bb + (size_t)kk * ldb + n4);
            __nv_bfloat162 h0, l0, h1, l1;
            cvt_hilo(v.x, v.y, h0, l0);
            cvt_hilo(v.z, v.w, h1, l1);
            *(__nv_bfloat162*)(Bh + kk * BPITCH + n4)     = h0;
            *(__nv_bfloat162*)(Bh + kk * BPITCH + n4 + 2) = h1;
            *(__nv_bfloat162*)(Bl + kk * BPITCH + n4)     = l0;
            *(__nv_bfloat162*)(Bl + kk * BPITCH + n4 + 2) = l1;
        }
        __syncthreads();

        // --- compute: 2 k16 steps ---
#pragma unroll
        for (int ks = 0; ks < 2; ks++) {
            uint32_t ahf[2][4], alf[2][4];
#pragma unroll
            for (int ms = 0; ms < 2; ms++) {
                int arow = wm + ms * 16 + (g & 1) * 8 + r;
                int acol = ks * 16 + (g >> 1) * 8;
                uint32_t ao = (uint32_t)(arow * (APITCH * 2) + acol * 2);
                ldsm_x4(ahf[ms][0], ahf[ms][1], ahf[ms][2], ahf[ms][3], ah_base + ao);
                ldsm_x4(alf[ms][0], alf[ms][1], alf[ms][2], alf[ms][3], al_base + ao);
            }
#pragma unroll
            for (int j2 = 0; j2 < 4; j2++) {
                int nb = wn + j2 * 16;
                int brow = ks * 16 + (g & 1) * 8 + r;
                int bcol = nb + (g >> 1) * 8;
                uint32_t bo = (uint32_t)(brow * (BPITCH * 2) + bcol * 2);
                uint32_t bhf[4], blf[4];
                ldsm_x4t(bhf[0], bhf[1], bhf[2], bhf[3], bh_base + bo);
                mma16816(acc[0][2 * j2],     ahf[0], bhf);
                mma16816(acc[0][2 * j2 + 1], ahf[0], bhf + 2);
                mma16816(acc[1][2 * j2],     ahf[1], bhf);
                mma16816(acc[1][2 * j2 + 1], ahf[1], bhf + 2);
                mma16816(acc[0][2 * j2],     alf[0], bhf);
                mma16816(acc[0][2 * j2 + 1], alf[0], bhf + 2);
                mma16816(acc[1][2 * j2],     alf[1], bhf);
                mma16816(acc[1][2 * j2 + 1], alf[1], bhf + 2);
                ldsm_x4t(blf[0], blf[1], blf[2], blf[3], bl_base + bo);
                mma16816(acc[0][2 * j2],     ahf[0], blf);
                mma16816(acc[0][2 * j2 + 1], ahf[0], blf + 2);
                mma16816(acc[1][2 * j2],     ahf[1], blf);
                mma16816(acc[1][2 * j2 + 1], ahf[1], blf + 2);
            }
        }
    }

    // --- epilogue: fp32 accumulators -> C ---
#pragma unroll
    for (int ms = 0; ms < 2; ms++) {
#pragma unroll
        for (int nj = 0; nj < 8; nj++) {
            int row0 = wm + ms * 16 + (lane >> 2);
            int col  = wn + nj * 8 + (lane & 3) * 2;
            *(float2*)(C + (size_t)row0 * ldc + col) =
                make_float2(acc[ms][nj][0], acc[ms][nj][1]);
            *(float2*)(C + (size_t)(row0 + 8) * ldc + col) =
                make_float2(acc[ms][nj][2], acc[ms][nj][3]);
        }
    }
}

// ---------------------------------------------------------------------------
// QKV projection: grid (16 row tiles, 48 heads). Heads 0..31 Q, 32..39 K, 40..47 V.
// ---------------------------------------------------------------------------
__global__ __launch_bounds__(256, 2) void qkv_mma_kernel(
    const float* __restrict__ x, const float* __restrict__ q_w,
    const float* __restrict__ kv_w)
{
    const int rowBlk = blockIdx.x;   // 0..15
    const int h = blockIdx.y;        // 0..47
    const float* A = x + (size_t)rowBlk * 128 * DMODEL;
    const float* B;
    float* C;
    int ldc;
    if (h < NQ) {
        B = q_w + (size_t)h * DMODEL * HD;
        C = g_q + (size_t)rowBlk * 128 * (NQ * HD) + h * HD;
        ldc = NQ * HD;
    } else if (h < NQ + NKV) {
        int kh = h - NQ;
        B = kv_w + (size_t)kh * DMODEL * HD;
        C = g_k + (size_t)rowBlk * 128 * (NKV * HD) + kh * HD;
        ldc = NKV * HD;
    } else {
        int vh = h - NQ - NKV;
        B = kv_w + (size_t)(NKV + vh) * DMODEL * HD;
        C = g_v + (size_t)rowBlk * 128 * (NKV * HD) + vh * HD;
        ldc = NKV * HD;
    }
    gemm_mma(A, DMODEL, B, HD, C, ldc, DMODEL);
}

// ---------------------------------------------------------------------------
// O projection: out[T,D] = g_o[T, N*H] @ o_w[N*H, D];  grid (32 colBlk, 16 rowBlk)
// ---------------------------------------------------------------------------
__global__ __launch_bounds__(256, 2) void oproj_mma_kernel(
    const float* __restrict__ o_w, float* __restrict__ out)
{
    const int colBlk = blockIdx.x;  // 0..31
    const int rowBlk = blockIdx.y;  // 0..15
    gemm_mma(g_o + (size_t)rowBlk * 128 * (NQ * HD), NQ * HD,
             o_w + colBlk * 128, DMODEL,
             out + (size_t)rowBlk * 128 * DMODEL + colBlk * 128, DMODEL,
             NQ * HD);
}

// ---------------------------------------------------------------------------
// RMSNorm (+ (1+scale) for q/k, plain for v) + RoPE (q/k only), in place.
// grid (48 heads, 2048 t), 128 threads.
// ---------------------------------------------------------------------------
__global__ __launch_bounds__(128) void normrope_kernel(
    const int* __restrict__ seg_pos, const float* __restrict__ q_scale,
    const float* __restrict__ k_scale)
{
    const int h = blockIdx.x;   // 0..47
    const int t = blockIdx.y;
    const int d = threadIdx.x;  // 0..127

    float* row;
    const float* sc;
    bool dorope;
    if (h < NQ)            { row = g_q + ((size_t)t * NQ + h) * HD;         sc = q_scale; dorope = true; }
    else if (h < NQ + NKV) { row = g_k + ((size_t)t * NKV + (h - NQ)) * HD; sc = k_scale; dorope = true; }
    else                   { row = g_v + ((size_t)t * NKV + (h - NQ - NKV)) * HD; sc = nullptr; dorope = false; }

    float v = row[d];
    float ss = v * v;
#pragma unroll
    for (int m = 16; m >= 1; m >>= 1) ss += __shfl_xor_sync(0xffffffffu, ss, m);
    __shared__ float red[4];
    if ((d & 31) == 0) red[d >> 5] = ss;
    __syncthreads();
    ss = red[0] + red[1] + red[2] + red[3];

    float rms = rsqrtf(ss * (1.0f / 128.0f) + 1e-6f);
    float scale = sc ? (1.0f + sc[d]) : 1.0f;
    float nv = v * rms * scale;

    if (!dorope) { row[d] = nv; return; }

    __shared__ float sh[128];
    sh[d] = nv;
    __syncthreads();
    if (d < 64) {
        float x1 = sh[d];
        float x2 = sh[d + 64];
        float pos = (float)seg_pos[t];
        float fraction = (2.0f * (float)d) * (1.0f / 128.0f);
        float timescale = powf(10000.0f, fraction);
        float ang = pos / timescale;
        float s = sinf(ang), c = cosf(ang);
        row[d]      = x1 * c - x2 * s;
        row[d + 64] = x2 * c + x1 * s;
    }
}

// ---------------------------------------------------------------------------
// Flash attention, 64x64 tiles, online softmax, causal (fp32 SIMT).
// grid (32 q-tiles, 32 heads), 256 threads, dynamic smem ~113KB.
// ---------------------------------------------------------------------------
#define FLASH_SMEM_FLOATS (8192 + 8192 + 8192 + 64 * 68)
#define FLASH_SMEM_BYTES  (FLASH_SMEM_FLOATS * 4)

__global__ __launch_bounds__(256) void flash_kernel()
{
    extern __shared__ float smem[];
    float* Qs = smem;             // [d][m]  128*64
    float* Ks = smem + 8192;      // [d][s]  128*64
    float* Vs = smem + 16384;     // [s][h]  64*128
    float* Ps = smem + 24576;     // [m][s]  64*68

    const int qt   = blockIdx.x;
    const int head = blockIdx.y;
    const int kvh  = head >> 2;
    const int tid  = threadIdx.x;
    const int tx = tid & 15;
    const int ty = tid >> 4;
    const int t0 = qt * 64;

#pragma unroll
    for (int i = 0; i < 8; i++) {
        int idx = tid + i * 256;
        int m  = idx >> 5;
        int d4 = (idx & 31) * 4;
        float4 v = *(const float4*)(g_q + ((size_t)(t0 + m) * NQ + head) * HD + d4);
        Qs[(d4 + 0) * 64 + m] = v.x;
        Qs[(d4 + 1) * 64 + m] = v.y;
        Qs[(d4 + 2) * 64 + m] = v.z;
        Qs[(d4 + 3) * 64 + m] = v.w;
    }

    float acc[4][8];
    float mrow[4], lrow[4];
#pragma unroll
    for (int i = 0; i < 4; i++) {
        mrow[i] = -INFINITY;
        lrow[i] = 0.f;
#pragma unroll
        for (int hh = 0; hh < 8; hh++) acc[i][hh] = 0.f;
    }

    const int ntiles = qt + 1;
    for (int j = 0; j < ntiles; j++) {
        const int s0 = j * 64;
        __syncthreads();

#pragma unroll
        for (int i = 0; i < 8; i++) {
            int idx = tid + i * 256;
            int s  = idx >> 5;
            int d4 = (idx & 31) * 4;
            size_t base = ((size_t)(s0 + s) * NKV + kvh) * HD + d4;
            float4 kv = *(const float4*)(g_k + base);
            Ks[(d4 + 0) * 64 + s] = kv.x;
            Ks[(d4 + 1) * 64 + s] = kv.y;
            Ks[(d4 + 2) * 64 + s] = kv.z;
            Ks[(d4 + 3) * 64 + s] = kv.w;
            *(float4*)&Vs[s * 128 + d4] = *(const float4*)(g_v + base);
        }
        __syncthreads();

        float sacc[4][4];
#pragma unroll
        for (int i = 0; i < 4; i++)
#pragma unroll
            for (int jj = 0; jj < 4; jj++) sacc[i][jj] = 0.f;

#pragma unroll 8
        for (int d = 0; d < 128; d++) {
            float4 qv = *(const float4*)(Qs + d * 64 + ty * 4);
            float4 kv = *(const float4*)(Ks + d * 64 + tx * 4);
            float qa[4] = {qv.x, qv.y, qv.z, qv.w};
            float kb[4] = {kv.x, kv.y, kv.z, kv.w};
#pragma unroll
            for (int i = 0; i < 4; i++)
#pragma unroll
                for (int jj = 0; jj < 4; jj++)
                    sacc[i][jj] = fmaf(qa[i], kb[jj], sacc[i][jj]);
        }

        const bool diag = (j == qt);
#pragma unroll
        for (int i = 0; i < 4; i++) {
            const int tg = t0 + ty * 4 + i;
            if (diag) {
#pragma unroll
                for (int jj = 0; jj < 4; jj++)
                    if (s0 + tx * 4 + jj > tg) sacc[i][jj] = -INFINITY;
            }
            float mt = fmaxf(fmaxf(sacc[i][0], sacc[i][1]), fmaxf(sacc[i][2], sacc[i][3]));
#pragma unroll
            for (int mm = 8; mm >= 1; mm >>= 1)
                mt = fmaxf(mt, __shfl_xor_sync(0xffffffffu, mt, mm));
            float mnew = fmaxf(mrow[i], mt);
            float alpha = expf(mrow[i] - mnew);
            float pv[4];
            float ps = 0.f;
#pragma unroll
            for (int jj = 0; jj < 4; jj++) {
                float p = expf(sacc[i][jj] - mnew);
                pv[jj] = p;
                ps += p;
            }
#pragma unroll
            for (int mm = 8; mm >= 1; mm >>= 1)
                ps += __shfl_xor_sync(0xffffffffu, ps, mm);
            lrow[i] = lrow[i] * alpha + ps;
            mrow[i] = mnew;
#pragma unroll
            for (int hh = 0; hh < 8; hh++) acc[i][hh] *= alpha;
            *(float4*)(Ps + (ty * 4 + i) * 68 + tx * 4) =
                make_float4(pv[0], pv[1], pv[2], pv[3]);
        }
        __syncthreads();

#pragma unroll 4
        for (int s = 0; s < 64; s++) {
            float4 v0 = *(const float4*)&Vs[s * 128 + tx * 8];
            float4 v1 = *(const float4*)&Vs[s * 128 + tx * 8 + 4];
#pragma unroll
            for (int i = 0; i < 4; i++) {
                float p = Ps[(ty * 4 + i) * 68 + s];
                acc[i][0] = fmaf(p, v0.x, acc[i][0]);
                acc[i][1] = fmaf(p, v0.y, acc[i][1]);
                acc[i][2] = fmaf(p, v0.z, acc[i][2]);
                acc[i][3] = fmaf(p, v0.w, acc[i][3]);
                acc[i][4] = fmaf(p, v1.x, acc[i][4]);
                acc[i][5] = fmaf(p, v1.y, acc[i][5]);
                acc[i][6] = fmaf(p, v1.z, acc[i][6]);
                acc[i][7] = fmaf(p, v1.w, acc[i][7]);
            }
        }
    }

#pragma unroll
    for (int i = 0; i < 4; i++) {
        float inv = 1.0f / lrow[i];
        float* op = g_o + ((size_t)(t0 + ty * 4 + i) * NQ + head) * HD + tx * 8;
        *(float4*)op =
            make_float4(acc[i][0] * inv, acc[i][1] * inv, acc[i][2] * inv, acc[i][3] * inv);
        *(float4*)(op + 4) =
            make_float4(acc[i][4] * inv, acc[i][5] * inv, acc[i][6] * inv, acc[i][7] * inv);
    }
}

// ---------------------------------------------------------------------------
extern "C" void kernel_launch(void* const* d_in, const int* in_sizes, int n_in,
                              void* d_out, int out_size)
{
    const float* x       = (const float*)d_in[0];
    const int*   seg     = (const int*)d_in[1];
    // d_in[2] = attn_mask (exactly causal; applied analytically)
    const float* q_w     = (const float*)d_in[3];
    const float* kv_w    = (const float*)d_in[4];
    const float* o_w     = (const float*)d_in[5];
    const float* q_scale = (const float*)d_in[6];
    const float* k_scale = (const float*)d_in[7];
    float* out = (float*)d_out;

    cudaFuncSetAttribute(flash_kernel, cudaFuncAttributeMaxDynamicSharedMemorySize,
                         FLASH_SMEM_BYTES);

    qkv_mma_kernel<<<dim3(16, 48), 256>>>(x, q_w, kv_w);
    normrope_kernel<<<dim3(48, TSEQ), 128>>>(seg, q_scale, k_scale);
    flash_kernel<<<dim3(32, 32), 256, FLASH_SMEM_BYTES>>>();
    oproj_mma_kernel<<<dim3(32, 16), 256>>>(o_w, out);
}